// round 6
// baseline (speedup 1.0000x reference)
#include <cuda_runtime.h>
#include <math.h>

#define NN 100000
#define NE 1600000
#define ET (NE + NN)
#define DH 64
#define NG 64
#define NB_SCAN 98   // ceil(NN/1024)

// ---- scratch (device globals) ----
__device__ __align__(16) float g_h[NN * DH];      // projected features (fp32)
__device__ __align__(16) float g_x[NN * DH];      // activated layer output / next input
__device__ __align__(16) float2 g_pe[ET];         // per-edge {p, src_bits}
__device__ float g_s[NN];                         // h . a_src per node
__device__ float g_d[NN];                         // h . a_dst per node
__device__ float g_vn[NG * DH];                   // pooled virtual-node features
__device__ int   g_cnt[NN];                       // in-degree (incl. self loop)
__device__ int   g_row[NN + 1];                   // CSR row offsets (by dst)
__device__ int   g_woff[NN];                      // working offsets for scatter
__device__ int   g_csrc[ET];                      // CSR: src node per edge slot
__device__ int   g_cdst[ET];                      // CSR: dst node per edge slot
__device__ int   g_bsum[128];

// ===========================================================================
// CSR build (edge_index constant across layers -> build once per launch)
// ===========================================================================
__global__ void k_initcnt() {
    int i = blockIdx.x * blockDim.x + threadIdx.x;
    if (i < NN) g_cnt[i] = 1;  // self loop
}

__global__ void k_hist(const int* __restrict__ ei) {
    int i = blockIdx.x * blockDim.x + threadIdx.x;
    if (i < NE) atomicAdd(&g_cnt[ei[NE + i]], 1);
}

__global__ void k_scan1() {
    __shared__ int sm[1024];
    int t = threadIdx.x;
    int idx = blockIdx.x * 1024 + t;
    int v = (idx < NN) ? g_cnt[idx] : 0;
    sm[t] = v;
    __syncthreads();
#pragma unroll
    for (int o = 1; o < 1024; o <<= 1) {
        int nv = (t >= o) ? sm[t - o] : 0;
        __syncthreads();
        sm[t] += nv;
        __syncthreads();
    }
    if (idx < NN) g_row[idx] = sm[t] - v;  // exclusive within block
    if (t == 1023) g_bsum[blockIdx.x] = sm[1023];
}

// fused: scan block sums locally in smem, then add to per-element offsets
__global__ void k_scan3() {
    __shared__ int sb[128];
    int t = threadIdx.x;
    if (t < 128) sb[t] = (t < NB_SCAN) ? g_bsum[t] : 0;
    __syncthreads();
#pragma unroll
    for (int o = 1; o < 128; o <<= 1) {
        int nv = (t >= o && t < 128) ? sb[t - o] : 0;
        __syncthreads();
        if (t < 128) sb[t] += nv;
        __syncthreads();
    }
    int idx = blockIdx.x * blockDim.x + t;
    if (idx < NN) {
        int blk = idx >> 10;
        int r = g_row[idx] + (blk ? sb[blk - 1] : 0);
        g_row[idx] = r;
        g_woff[idx] = r;
    }
    if (idx == 0) g_row[NN] = ET;
}

__global__ void k_scatter(const int* __restrict__ ei) {
    int i = blockIdx.x * blockDim.x + threadIdx.x;
    if (i >= ET) return;
    int s, d;
    if (i < NE) { s = ei[i]; d = ei[NE + i]; }
    else        { s = d = i - NE; }
    int pos = atomicAdd(&g_woff[d], 1);
    g_csrc[pos] = s;
    g_cdst[pos] = d;
}

// ===========================================================================
// matmul: 64 nodes x 64 cols per 256-thread block (R3-proven version).
// ===========================================================================
__global__ void __launch_bounds__(256) k_matmul(
        const float* __restrict__ xin, const float* __restrict__ W,
        const float* __restrict__ bias, float* __restrict__ dst,
        const float* __restrict__ a_src, const float* __restrict__ a_dst) {
    __shared__ float Ws[DH * DH];
    __shared__ float xs[64 * DH];
    int t = threadIdx.x;
#pragma unroll
    for (int i = 0; i < 16; i++) Ws[t + 256 * i] = W[t + 256 * i];
    int base = blockIdx.x * 64;
#pragma unroll
    for (int i = 0; i < 16; i++) {
        int idx = t + 256 * i;  // 0..4095
        int g = base * DH + idx;
        xs[idx] = (g < NN * DH) ? xin[g] : 0.f;
    }
    __syncthreads();

    int tx = t & 31;   // lane -> cols 2tx, 2tx+1
    int ty = t >> 5;   // warp -> 8 nodes

    float b0 = bias ? bias[2 * tx] : 0.f;
    float b1 = bias ? bias[2 * tx + 1] : 0.f;
    float acc[8][2];
#pragma unroll
    for (int j = 0; j < 8; j++) { acc[j][0] = b0; acc[j][1] = b1; }

#pragma unroll
    for (int k = 0; k < DH; k += 4) {
        float4 xv[8];
#pragma unroll
        for (int j = 0; j < 8; j++)
            xv[j] = *(const float4*)&xs[(ty * 8 + j) * DH + k];
#pragma unroll
        for (int kk = 0; kk < 4; kk++) {
            float2 w = *(const float2*)&Ws[(k + kk) * DH + 2 * tx];
#pragma unroll
            for (int j = 0; j < 8; j++) {
                float xvv = (&xv[j].x)[kk];
                acc[j][0] = fmaf(xvv, w.x, acc[j][0]);
                acc[j][1] = fmaf(xvv, w.y, acc[j][1]);
            }
        }
    }

    float as0 = 0.f, as1 = 0.f, ad0 = 0.f, ad1 = 0.f;
    if (a_src) { as0 = a_src[2 * tx]; as1 = a_src[2 * tx + 1];
                 ad0 = a_dst[2 * tx]; ad1 = a_dst[2 * tx + 1]; }

#pragma unroll
    for (int j = 0; j < 8; j++) {
        int n = base + ty * 8 + j;
        if (n >= NN) break;
        *(float2*)&dst[(size_t)n * DH + 2 * tx] = make_float2(acc[j][0], acc[j][1]);
        if (a_src) {
            float ss = acc[j][0] * as0 + acc[j][1] * as1;
            float dd = acc[j][0] * ad0 + acc[j][1] * ad1;
#pragma unroll
            for (int o = 16; o; o >>= 1) {
                ss += __shfl_xor_sync(0xffffffffu, ss, o);
                dd += __shfl_xor_sync(0xffffffffu, dd, o);
            }
            if (tx == 0) { g_s[n] = ss; g_d[n] = dd; }
        }
    }
}

// ===========================================================================
// Per-edge attention weight (shift-free softmax numerator), edge-parallel.
// g_pe[j] = { exp(leaky(g_s[src]+g_d[dst])), src_bits }
// ===========================================================================
__global__ void k_edgep() {
    int j = blockIdx.x * blockDim.x + threadIdx.x;
    if (j >= ET) return;
    int src = g_csrc[j];
    int dst = g_cdst[j];
    float e = __ldg(&g_s[src]) + __ldg(&g_d[dst]);
    e = fmaxf(e, 0.2f * e);          // leaky_relu(0.2)
    float p = __expf(fminf(e, 60.f));
    g_pe[j] = make_float2(p, __int_as_float(src));
}

// ===========================================================================
// Aggregation: two nodes per warp (16 lanes each, 4 fp32 cols/lane).
// Inner loop: LDG.64 pe -> LDG.128 h -> 4 FMA + 1 add. Unrolled x4.
// ===========================================================================
__global__ void __launch_bounds__(256) k_agg(const float* __restrict__ bias,
                                             float* __restrict__ outp) {
    int w = threadIdx.x >> 5, lane = threadIdx.x & 31;
    int half = lane >> 4, hl = lane & 15;
    int n = blockIdx.x * 16 + w * 2 + half;
    bool valid = n < NN;
    int rs = valid ? g_row[n] : 0;
    int deg = valid ? g_row[n + 1] - rs : 0;

    const float4* __restrict__ hp = (const float4*)g_h;
    float s = 0.f;
    float4 a = make_float4(0.f, 0.f, 0.f, 0.f);

    int j = 0;
    for (; j + 4 <= deg; j += 4) {
        float2 pe0 = __ldg(&g_pe[rs + j]);
        float2 pe1 = __ldg(&g_pe[rs + j + 1]);
        float2 pe2 = __ldg(&g_pe[rs + j + 2]);
        float2 pe3 = __ldg(&g_pe[rs + j + 3]);
        float4 h0 = __ldg(&hp[__float_as_int(pe0.y) * 16 + hl]);
        float4 h1 = __ldg(&hp[__float_as_int(pe1.y) * 16 + hl]);
        float4 h2 = __ldg(&hp[__float_as_int(pe2.y) * 16 + hl]);
        float4 h3 = __ldg(&hp[__float_as_int(pe3.y) * 16 + hl]);
        s += (pe0.x + pe1.x) + (pe2.x + pe3.x);
        a.x = fmaf(pe0.x, h0.x, a.x); a.y = fmaf(pe0.x, h0.y, a.y);
        a.z = fmaf(pe0.x, h0.z, a.z); a.w = fmaf(pe0.x, h0.w, a.w);
        a.x = fmaf(pe1.x, h1.x, a.x); a.y = fmaf(pe1.x, h1.y, a.y);
        a.z = fmaf(pe1.x, h1.z, a.z); a.w = fmaf(pe1.x, h1.w, a.w);
        a.x = fmaf(pe2.x, h2.x, a.x); a.y = fmaf(pe2.x, h2.y, a.y);
        a.z = fmaf(pe2.x, h2.z, a.z); a.w = fmaf(pe2.x, h2.w, a.w);
        a.x = fmaf(pe3.x, h3.x, a.x); a.y = fmaf(pe3.x, h3.y, a.y);
        a.z = fmaf(pe3.x, h3.z, a.z); a.w = fmaf(pe3.x, h3.w, a.w);
    }
    for (; j < deg; j++) {
        float2 pe = __ldg(&g_pe[rs + j]);
        float4 h0 = __ldg(&hp[__float_as_int(pe.y) * 16 + hl]);
        s += pe.x;
        a.x = fmaf(pe.x, h0.x, a.x); a.y = fmaf(pe.x, h0.y, a.y);
        a.z = fmaf(pe.x, h0.z, a.z); a.w = fmaf(pe.x, h0.w, a.w);
    }

    if (!valid) return;
    float inv = 1.f / (s + 1e-16f);
    float4 b4 = *(const float4*)&bias[4 * hl];
    float v0 = fmaf(a.x, inv, b4.x);
    float v1 = fmaf(a.y, inv, b4.y);
    float v2 = fmaf(a.z, inv, b4.z);
    float v3 = fmaf(a.w, inv, b4.w);
    v0 = v0 > 0.f ? v0 : 0.01f * v0;
    v1 = v1 > 0.f ? v1 : 0.01f * v1;
    v2 = v2 > 0.f ? v2 : 0.01f * v2;
    v3 = v3 > 0.f ? v3 : 0.01f * v3;
    *(float4*)&outp[(size_t)n * DH + 4 * hl] = make_float4(v0, v1, v2, v3);
}

// ---- virtual node: init with embedding, pool (batch is sorted) ----
__global__ void k_vninit(const float* __restrict__ emb) {
    int i = blockIdx.x * blockDim.x + threadIdx.x;
    if (i < NG * DH) g_vn[i] = emb[i & 63];
}

__global__ void k_pool(const int* __restrict__ batch) {
    int c = threadIdx.x;  // 0..63
    int n0 = blockIdx.x * 256;
    int n1 = n0 + 256; if (n1 > NN) n1 = NN;
    if (n0 >= NN) return;
    float acc = 0.f;
    int cur = batch[n0];
    for (int n = n0; n < n1; n++) {
        int bb = batch[n];
        if (bb != cur) { atomicAdd(&g_vn[cur * DH + c], acc); acc = 0.f; cur = bb; }
        acc += g_x[(size_t)n * DH + c];
    }
    atomicAdd(&g_vn[cur * DH + c], acc);
}

// ---- 4-layer MLP on vn, one block (64 threads) per graph ----
__global__ void k_vnmlp(const float* __restrict__ W1, const float* __restrict__ b1,
                        const float* __restrict__ W2, const float* __restrict__ b2,
                        const float* __restrict__ W3, const float* __restrict__ b3,
                        const float* __restrict__ W4, const float* __restrict__ b4,
                        float* __restrict__ outp) {
    __shared__ float r[64];
    int g = blockIdx.x, c = threadIdx.x;
    r[c] = g_vn[g * DH + c];
    __syncthreads();
    const float* Ws[4] = {W1, W2, W3, W4};
    const float* bs[4] = {b1, b2, b3, b4};
    for (int L = 0; L < 4; L++) {
        float acc = bs[L][c];
        for (int k = 0; k < 64; k++) acc = fmaf(r[k], Ws[L][k * 64 + c], acc);
        __syncthreads();
        r[c] = acc > 0.f ? acc : 0.f;
        __syncthreads();
    }
    outp[g * DH + c] = r[c];
}

extern "C" void kernel_launch(void* const* d_in, const int* in_sizes, int n_in,
                              void* d_out, int out_size) {
    const float* x     = (const float*)d_in[0];
    const int*   ei    = (const int*)d_in[1];
    const int*   batch = (const int*)d_in[2];
    int o = (in_sizes[3] <= 16) ? 4 : 3;
    const float* W[3], *asr[3], *adt[3], *bb[3];
    for (int i = 0; i < 3; i++) {
        W[i]   = (const float*)d_in[o + 4 * i + 0];
        asr[i] = (const float*)d_in[o + 4 * i + 1];
        adt[i] = (const float*)d_in[o + 4 * i + 2];
        bb[i]  = (const float*)d_in[o + 4 * i + 3];
    }
    const float* Wout = (const float*)d_in[o + 12];
    const float* bout = (const float*)d_in[o + 13];
    const float* vne  = (const float*)d_in[o + 14];
    const float* Wm1 = (const float*)d_in[o + 15], *bm1 = (const float*)d_in[o + 16];
    const float* Wm2 = (const float*)d_in[o + 17], *bm2 = (const float*)d_in[o + 18];
    const float* Wf1 = (const float*)d_in[o + 19], *bf1 = (const float*)d_in[o + 20];
    const float* Wf2 = (const float*)d_in[o + 21], *bf2 = (const float*)d_in[o + 22];

    float *px = nullptr, *ph = nullptr;
    cudaGetSymbolAddress((void**)&px, g_x);
    cudaGetSymbolAddress((void**)&ph, g_h);
    float* out = (float*)d_out;

    // ---- CSR build (once; reused by all 3 layers) ----
    k_initcnt<<<(NN + 255) / 256, 256>>>();
    k_hist<<<(NE + 255) / 256, 256>>>(ei);
    k_scan1<<<NB_SCAN, 1024>>>();
    k_scan3<<<(NN + 255) / 256, 256>>>();
    k_scatter<<<(ET + 255) / 256, 256>>>(ei);

    // ---- 3 GAT layers ----
    const float* cur = x;
    for (int L = 0; L < 3; L++) {
        k_matmul<<<(NN + 63) / 64, 256>>>(cur, W[L], nullptr, ph, asr[L], adt[L]);
        k_edgep<<<(ET + 255) / 256, 256>>>();
        k_agg<<<(NN + 15) / 16, 256>>>(bb[L], px);
        cur = px;
    }

    // final node projection (fp32 out)
    k_matmul<<<(NN + 63) / 64, 256>>>(px, Wout, bout, out, nullptr, nullptr);

    // virtual node branch
    k_vninit<<<(NG * DH + 255) / 256, 256>>>(vne);
    k_pool<<<(NN + 255) / 256, 64>>>(batch);
    k_vnmlp<<<NG, 64>>>(Wm1, bm1, Wm2, bm2, Wf1, bf1, Wf2, bf2, out + (size_t)NN * DH);
}

// round 7
// speedup vs baseline: 1.0824x; 1.0824x over previous
#include <cuda_runtime.h>
#include <cuda_fp16.h>
#include <math.h>

#define NN 100000
#define NE 1600000
#define ET (NE + NN)
#define DH 64
#define NG 64
#define NB_SCAN 98   // ceil(NN/1024)

// ---- scratch (device globals) ----
__device__ __align__(16) __half2 g_h2[NN * 32];   // projected features (fp16, 2 cols/elt)
__device__ __align__(16) float g_x[NN * DH];      // activated layer output / next input
__device__ __align__(16) float2 g_pe[ET];         // per-edge {p, src_bits}
__device__ float g_s[NN];                         // h . a_src per node
__device__ float g_d[NN];                         // h . a_dst per node
__device__ float g_vn[NG * DH];                   // pooled virtual-node features
__device__ int   g_cnt[NN];                       // in-degree (incl. self loop)
__device__ int   g_row[NN + 1];                   // CSR row offsets (by dst)
__device__ int   g_woff[NN];                      // working offsets for scatter
__device__ int   g_csrc[ET];                      // CSR: src node per edge slot
__device__ int   g_cdst[ET];                      // CSR: dst node per edge slot
__device__ int   g_bsum[128];

// ===========================================================================
// CSR build (edge_index constant across layers -> build once per launch)
// ===========================================================================
__global__ void k_initcnt() {
    int i = blockIdx.x * blockDim.x + threadIdx.x;
    if (i < NN) g_cnt[i] = 1;  // self loop
}

__global__ void k_hist(const int* __restrict__ ei) {
    int i = blockIdx.x * blockDim.x + threadIdx.x;
    if (i < NE) atomicAdd(&g_cnt[ei[NE + i]], 1);
}

__global__ void k_scan1() {
    __shared__ int sm[1024];
    int t = threadIdx.x;
    int idx = blockIdx.x * 1024 + t;
    int v = (idx < NN) ? g_cnt[idx] : 0;
    sm[t] = v;
    __syncthreads();
#pragma unroll
    for (int o = 1; o < 1024; o <<= 1) {
        int nv = (t >= o) ? sm[t - o] : 0;
        __syncthreads();
        sm[t] += nv;
        __syncthreads();
    }
    if (idx < NN) g_row[idx] = sm[t] - v;  // exclusive within block
    if (t == 1023) g_bsum[blockIdx.x] = sm[1023];
}

// fused: scan block sums locally in smem, then add to per-element offsets
__global__ void k_scan3() {
    __shared__ int sb[128];
    int t = threadIdx.x;
    if (t < 128) sb[t] = (t < NB_SCAN) ? g_bsum[t] : 0;
    __syncthreads();
#pragma unroll
    for (int o = 1; o < 128; o <<= 1) {
        int nv = (t >= o && t < 128) ? sb[t - o] : 0;
        __syncthreads();
        if (t < 128) sb[t] += nv;
        __syncthreads();
    }
    int idx = blockIdx.x * blockDim.x + t;
    if (idx < NN) {
        int blk = idx >> 10;
        int r = g_row[idx] + (blk ? sb[blk - 1] : 0);
        g_row[idx] = r;
        g_woff[idx] = r;
    }
    if (idx == 0) g_row[NN] = ET;
}

__global__ void k_scatter(const int* __restrict__ ei) {
    int i = blockIdx.x * blockDim.x + threadIdx.x;
    if (i >= ET) return;
    int s, d;
    if (i < NE) { s = ei[i]; d = ei[NE + i]; }
    else        { s = d = i - NE; }
    int pos = atomicAdd(&g_woff[d], 1);
    g_csrc[pos] = s;
    g_cdst[pos] = d;
}

// ===========================================================================
// matmul: 64 nodes x 64 cols per 256-thread block (R3/R5-proven version).
// ===========================================================================
__global__ void __launch_bounds__(256) k_matmul(
        const float* __restrict__ xin, const float* __restrict__ W,
        const float* __restrict__ bias, float* __restrict__ dstF,
        __half2* __restrict__ dstH,
        const float* __restrict__ a_src, const float* __restrict__ a_dst) {
    __shared__ float Ws[DH * DH];
    __shared__ float xs[64 * DH];
    int t = threadIdx.x;
#pragma unroll
    for (int i = 0; i < 16; i++) Ws[t + 256 * i] = W[t + 256 * i];
    int base = blockIdx.x * 64;
#pragma unroll
    for (int i = 0; i < 16; i++) {
        int idx = t + 256 * i;  // 0..4095
        int g = base * DH + idx;
        xs[idx] = (g < NN * DH) ? xin[g] : 0.f;
    }
    __syncthreads();

    int tx = t & 31;   // lane -> cols 2tx, 2tx+1
    int ty = t >> 5;   // warp -> 8 nodes

    float b0 = bias ? bias[2 * tx] : 0.f;
    float b1 = bias ? bias[2 * tx + 1] : 0.f;
    float acc[8][2];
#pragma unroll
    for (int j = 0; j < 8; j++) { acc[j][0] = b0; acc[j][1] = b1; }

#pragma unroll
    for (int k = 0; k < DH; k += 4) {
        float4 xv[8];
#pragma unroll
        for (int j = 0; j < 8; j++)
            xv[j] = *(const float4*)&xs[(ty * 8 + j) * DH + k];
#pragma unroll
        for (int kk = 0; kk < 4; kk++) {
            float2 w = *(const float2*)&Ws[(k + kk) * DH + 2 * tx];
#pragma unroll
            for (int j = 0; j < 8; j++) {
                float xvv = (&xv[j].x)[kk];
                acc[j][0] = fmaf(xvv, w.x, acc[j][0]);
                acc[j][1] = fmaf(xvv, w.y, acc[j][1]);
            }
        }
    }

    float as0 = 0.f, as1 = 0.f, ad0 = 0.f, ad1 = 0.f;
    if (a_src) { as0 = a_src[2 * tx]; as1 = a_src[2 * tx + 1];
                 ad0 = a_dst[2 * tx]; ad1 = a_dst[2 * tx + 1]; }

#pragma unroll
    for (int j = 0; j < 8; j++) {
        int n = base + ty * 8 + j;
        if (n >= NN) break;
        if (dstH) g_h2[(size_t)n * 32 + tx] = __floats2half2_rn(acc[j][0], acc[j][1]);
        if (dstF) *(float2*)&dstF[(size_t)n * DH + 2 * tx] = make_float2(acc[j][0], acc[j][1]);
        if (a_src) {
            float ss = acc[j][0] * as0 + acc[j][1] * as1;
            float dd = acc[j][0] * ad0 + acc[j][1] * ad1;
#pragma unroll
            for (int o = 16; o; o >>= 1) {
                ss += __shfl_xor_sync(0xffffffffu, ss, o);
                dd += __shfl_xor_sync(0xffffffffu, dd, o);
            }
            if (tx == 0) { g_s[n] = ss; g_d[n] = dd; }
        }
    }
}

// ===========================================================================
// Per-edge attention weight (shift-free softmax numerator), edge-parallel.
// g_pe[j] = { exp(leaky(g_s[src]+g_d[dst])), src_bits }
// ===========================================================================
__global__ void k_edgep() {
    int j = blockIdx.x * blockDim.x + threadIdx.x;
    if (j >= ET) return;
    int src = g_csrc[j];
    int dst = g_cdst[j];
    float e = __ldg(&g_s[src]) + __ldg(&g_d[dst]);
    e = fmaxf(e, 0.2f * e);          // leaky_relu(0.2)
    float p = __expf(fminf(e, 60.f));
    g_pe[j] = make_float2(p, __int_as_float(src));
}

// ===========================================================================
// Aggregation: two nodes per warp (16 lanes each, 4 cols/lane via uint2=2xhalf2).
// Inner loop: LDG.64 pe -> LDG.64 h2 -> 2 cvt + 4 FMA + 1 add. Unrolled x4.
// ===========================================================================
__global__ void __launch_bounds__(256) k_agg(const float* __restrict__ bias,
                                             float* __restrict__ outp) {
    int w = threadIdx.x >> 5, lane = threadIdx.x & 31;
    int half = lane >> 4, hl = lane & 15;
    int n = blockIdx.x * 16 + w * 2 + half;
    bool valid = n < NN;
    int rs = valid ? g_row[n] : 0;
    int deg = valid ? g_row[n + 1] - rs : 0;

    const uint2* __restrict__ hp = (const uint2*)g_h2;
    float s = 0.f;
    float a0 = 0.f, a1 = 0.f, a2 = 0.f, a3 = 0.f;

    int j = 0;
    for (; j + 4 <= deg; j += 4) {
        float2 pe0 = __ldg(&g_pe[rs + j]);
        float2 pe1 = __ldg(&g_pe[rs + j + 1]);
        float2 pe2 = __ldg(&g_pe[rs + j + 2]);
        float2 pe3 = __ldg(&g_pe[rs + j + 3]);
        uint2 h0 = __ldg(&hp[__float_as_int(pe0.y) * 16 + hl]);
        uint2 h1 = __ldg(&hp[__float_as_int(pe1.y) * 16 + hl]);
        uint2 h2 = __ldg(&hp[__float_as_int(pe2.y) * 16 + hl]);
        uint2 h3 = __ldg(&hp[__float_as_int(pe3.y) * 16 + hl]);
        s += (pe0.x + pe1.x) + (pe2.x + pe3.x);
        float2 fa, fb;
        fa = __half22float2(*(__half2*)&h0.x); fb = __half22float2(*(__half2*)&h0.y);
        a0 = fmaf(pe0.x, fa.x, a0); a1 = fmaf(pe0.x, fa.y, a1);
        a2 = fmaf(pe0.x, fb.x, a2); a3 = fmaf(pe0.x, fb.y, a3);
        fa = __half22float2(*(__half2*)&h1.x); fb = __half22float2(*(__half2*)&h1.y);
        a0 = fmaf(pe1.x, fa.x, a0); a1 = fmaf(pe1.x, fa.y, a1);
        a2 = fmaf(pe1.x, fb.x, a2); a3 = fmaf(pe1.x, fb.y, a3);
        fa = __half22float2(*(__half2*)&h2.x); fb = __half22float2(*(__half2*)&h2.y);
        a0 = fmaf(pe2.x, fa.x, a0); a1 = fmaf(pe2.x, fa.y, a1);
        a2 = fmaf(pe2.x, fb.x, a2); a3 = fmaf(pe2.x, fb.y, a3);
        fa = __half22float2(*(__half2*)&h3.x); fb = __half22float2(*(__half2*)&h3.y);
        a0 = fmaf(pe3.x, fa.x, a0); a1 = fmaf(pe3.x, fa.y, a1);
        a2 = fmaf(pe3.x, fb.x, a2); a3 = fmaf(pe3.x, fb.y, a3);
    }
    for (; j < deg; j++) {
        float2 pe = __ldg(&g_pe[rs + j]);
        uint2 h0 = __ldg(&hp[__float_as_int(pe.y) * 16 + hl]);
        s += pe.x;
        float2 fa = __half22float2(*(__half2*)&h0.x);
        float2 fb = __half22float2(*(__half2*)&h0.y);
        a0 = fmaf(pe.x, fa.x, a0); a1 = fmaf(pe.x, fa.y, a1);
        a2 = fmaf(pe.x, fb.x, a2); a3 = fmaf(pe.x, fb.y, a3);
    }

    if (!valid) return;
    float inv = 1.f / (s + 1e-16f);
    float4 b4 = *(const float4*)&bias[4 * hl];
    float v0 = fmaf(a0, inv, b4.x);
    float v1 = fmaf(a1, inv, b4.y);
    float v2 = fmaf(a2, inv, b4.z);
    float v3 = fmaf(a3, inv, b4.w);
    v0 = v0 > 0.f ? v0 : 0.01f * v0;
    v1 = v1 > 0.f ? v1 : 0.01f * v1;
    v2 = v2 > 0.f ? v2 : 0.01f * v2;
    v3 = v3 > 0.f ? v3 : 0.01f * v3;
    *(float4*)&outp[(size_t)n * DH + 4 * hl] = make_float4(v0, v1, v2, v3);
}

// ---- virtual node: init with embedding, pool (batch is sorted) ----
__global__ void k_vninit(const float* __restrict__ emb) {
    int i = blockIdx.x * blockDim.x + threadIdx.x;
    if (i < NG * DH) g_vn[i] = emb[i & 63];
}

__global__ void k_pool(const int* __restrict__ batch) {
    int c = threadIdx.x;  // 0..63
    int n0 = blockIdx.x * 256;
    int n1 = n0 + 256; if (n1 > NN) n1 = NN;
    if (n0 >= NN) return;
    float acc = 0.f;
    int cur = batch[n0];
    for (int n = n0; n < n1; n++) {
        int bb = batch[n];
        if (bb != cur) { atomicAdd(&g_vn[cur * DH + c], acc); acc = 0.f; cur = bb; }
        acc += g_x[(size_t)n * DH + c];
    }
    atomicAdd(&g_vn[cur * DH + c], acc);
}

// ---- 4-layer MLP on vn, one block (64 threads) per graph ----
__global__ void k_vnmlp(const float* __restrict__ W1, const float* __restrict__ b1,
                        const float* __restrict__ W2, const float* __restrict__ b2,
                        const float* __restrict__ W3, const float* __restrict__ b3,
                        const float* __restrict__ W4, const float* __restrict__ b4,
                        float* __restrict__ outp) {
    __shared__ float r[64];
    int g = blockIdx.x, c = threadIdx.x;
    r[c] = g_vn[g * DH + c];
    __syncthreads();
    const float* Ws[4] = {W1, W2, W3, W4};
    const float* bs[4] = {b1, b2, b3, b4};
    for (int L = 0; L < 4; L++) {
        float acc = bs[L][c];
        for (int k = 0; k < 64; k++) acc = fmaf(r[k], Ws[L][k * 64 + c], acc);
        __syncthreads();
        r[c] = acc > 0.f ? acc : 0.f;
        __syncthreads();
    }
    outp[g * DH + c] = r[c];
}

extern "C" void kernel_launch(void* const* d_in, const int* in_sizes, int n_in,
                              void* d_out, int out_size) {
    const float* x     = (const float*)d_in[0];
    const int*   ei    = (const int*)d_in[1];
    const int*   batch = (const int*)d_in[2];
    int o = (in_sizes[3] <= 16) ? 4 : 3;
    const float* W[3], *asr[3], *adt[3], *bb[3];
    for (int i = 0; i < 3; i++) {
        W[i]   = (const float*)d_in[o + 4 * i + 0];
        asr[i] = (const float*)d_in[o + 4 * i + 1];
        adt[i] = (const float*)d_in[o + 4 * i + 2];
        bb[i]  = (const float*)d_in[o + 4 * i + 3];
    }
    const float* Wout = (const float*)d_in[o + 12];
    const float* bout = (const float*)d_in[o + 13];
    const float* vne  = (const float*)d_in[o + 14];
    const float* Wm1 = (const float*)d_in[o + 15], *bm1 = (const float*)d_in[o + 16];
    const float* Wm2 = (const float*)d_in[o + 17], *bm2 = (const float*)d_in[o + 18];
    const float* Wf1 = (const float*)d_in[o + 19], *bf1 = (const float*)d_in[o + 20];
    const float* Wf2 = (const float*)d_in[o + 21], *bf2 = (const float*)d_in[o + 22];

    float *px = nullptr;
    __half2* ph2 = nullptr;
    cudaGetSymbolAddress((void**)&px, g_x);
    cudaGetSymbolAddress((void**)&ph2, g_h2);
    float* out = (float*)d_out;

    // ---- CSR build (once; reused by all 3 layers) ----
    k_initcnt<<<(NN + 255) / 256, 256>>>();
    k_hist<<<(NE + 255) / 256, 256>>>(ei);
    k_scan1<<<NB_SCAN, 1024>>>();
    k_scan3<<<(NN + 255) / 256, 256>>>();
    k_scatter<<<(ET + 255) / 256, 256>>>(ei);

    // ---- 3 GAT layers ----
    const float* cur = x;
    for (int L = 0; L < 3; L++) {
        k_matmul<<<(NN + 63) / 64, 256>>>(cur, W[L], nullptr, nullptr, ph2, asr[L], adt[L]);
        k_edgep<<<(ET + 255) / 256, 256>>>();
        k_agg<<<(NN + 15) / 16, 256>>>(bb[L], px);
        cur = px;
    }

    // final node projection (fp32 out)
    k_matmul<<<(NN + 63) / 64, 256>>>(px, Wout, bout, out, nullptr, nullptr, nullptr);

    // virtual node branch
    k_vninit<<<(NG * DH + 255) / 256, 256>>>(vne);
    k_pool<<<(NN + 255) / 256, 64>>>(batch);
    k_vnmlp<<<NG, 64>>>(Wm1, bm1, Wm2, bm2, Wf1, bf1, Wf2, bf2, out + (size_t)NN * DH);
}